// round 13
// baseline (speedup 1.0000x reference)
#include <cuda_runtime.h>
#include <math.h>

// ===========================================================================
// Problem constants
// ===========================================================================
#define BB 8
#define MM 144
#define M16 16
#define NN 500

// L0: C=128 H=48 W=64 | L1: C=64 H=96 W=128 | L2: C=32 H=192 W=256
#define PX0 (8*48*64)     /* 24576  */
#define PX1 (8*96*128)    /* 98304  */
#define PX2 (8*192*256)   /* 393216 */

// strips: PPT=2 -> warp covers 64 consecutive x; ONE strip per warp
#define ST0 (8*48)        /* 384  */
#define ST1 (8*96*2)      /* 1536 */
#define ST2 (8*192*4)     /* 6144 */
#define NSTRIPS (ST0+ST1+ST2)   /* 8064 */
#define NCTAS (NSTRIPS/4)       /* 2016 CTAs x 4 warps, 1 strip/warp */
#define NMEGA (BB*M16)          /* 128 mega CTAs (bids 0..127) */

// Gram/unc maps: per pixel a 32B record {S,R,D,G | A,U,0,0} as two float4
__device__ float4 g_maps[(PX0 + PX1 + PX2) * 2];
__device__ float  g_Tcur[BB * M16 * 12];
__device__ float  g_costs[BB * M16];
__device__ int    g_done[3];

// ===========================================================================
// Threefry2x32 (JAX-compatible, 20 rounds)
// ===========================================================================
__host__ __device__ inline void tf2x32(unsigned k0, unsigned k1,
                                       unsigned& x0, unsigned& x1) {
    unsigned ks2 = k0 ^ k1 ^ 0x1BD11BDAu;
    x0 += k0; x1 += k1;
#define TF_RND(r) { x0 += x1; x1 = (x1 << (r)) | (x1 >> (32 - (r))); x1 ^= x0; }
    TF_RND(13) TF_RND(15) TF_RND(26) TF_RND(6)
    x0 += k1; x1 += ks2 + 1u;
    TF_RND(17) TF_RND(29) TF_RND(16) TF_RND(24)
    x0 += ks2; x1 += k0 + 2u;
    TF_RND(13) TF_RND(15) TF_RND(26) TF_RND(6)
    x0 += k0; x1 += k1 + 3u;
    TF_RND(17) TF_RND(29) TF_RND(16) TF_RND(24)
    x0 += k1; x1 += ks2 + 4u;
    TF_RND(13) TF_RND(15) TF_RND(26) TF_RND(6)
    x0 += ks2; x1 += k0 + 5u;
#undef TF_RND
}

struct TFKeys {
    unsigned hk0, hk1;
    unsigned ik0[9], ik1[9];
};

// XLA ErfInv (float32, Giles polynomial)
__device__ inline float erfinv_x(float x) {
    float w = -log1pf(-x * x);
    float p;
    if (w < 5.0f) {
        w = w - 2.5f;
        p = 2.81022636e-08f;
        p = fmaf(p, w, 3.43273939e-07f);
        p = fmaf(p, w, -3.5233877e-06f);
        p = fmaf(p, w, -4.39150654e-06f);
        p = fmaf(p, w, 0.00021858087f);
        p = fmaf(p, w, -0.00125372503f);
        p = fmaf(p, w, -0.00417768164f);
        p = fmaf(p, w, 0.246640727f);
        p = fmaf(p, w, 1.50140941f);
    } else {
        w = sqrtf(w) - 3.0f;
        p = -0.000200214257f;
        p = fmaf(p, w, 0.000100950558f);
        p = fmaf(p, w, 0.00134934322f);
        p = fmaf(p, w, -0.00367342844f);
        p = fmaf(p, w, 0.00573950773f);
        p = fmaf(p, w, -0.0076224613f);
        p = fmaf(p, w, 0.00943887047f);
        p = fmaf(p, w, 1.00167406f);
        p = fmaf(p, w, 2.83297682f);
    }
    return p * x;
}

// jax.random.normal, partitionable threefry: bits[i] = x0 ^ x1 of enc(key,(0,i))
__device__ inline float tf_normal(unsigned k0, unsigned k1, unsigned idx) {
    unsigned x0 = 0u, x1 = idx;
    tf2x32(k0, k1, x0, x1);
    unsigned bits = x0 ^ x1;
    float f = __uint_as_float((bits >> 9) | 0x3f800000u) - 1.0f;
    const float lo = -0.99999994f;
    float u = fmaxf(lo, f * 2.0f + lo);
    return 1.4142135623730951f * erfinv_x(u);
}

// ===========================================================================
// SE(3) helpers — affine 3x4 (12-float)
// ===========================================================================
__device__ inline void se3exp12(const float xi[6], float T[12]) {
    float t0 = xi[0], t1 = xi[1], t2 = xi[2];
    float w0 = xi[3], w1 = xi[4], w2 = xi[5];
    float nw = sqrtf(w0 * w0 + w1 * w1 + w2 * w2);
    float theta = fmaxf(nw, 1e-8f);
    float a0 = w0 / theta, a1 = w1 / theta, a2 = w2 / theta;
    float K[9] = { 0.f, -a2,  a1,
                   a2,  0.f, -a0,
                  -a1,  a0,  0.f };
    float KK[9];
#pragma unroll
    for (int i = 0; i < 3; ++i)
#pragma unroll
        for (int j = 0; j < 3; ++j)
            KK[i * 3 + j] = K[i * 3 + 0] * K[0 * 3 + j]
                          + K[i * 3 + 1] * K[1 * 3 + j]
                          + K[i * 3 + 2] * K[2 * 3 + j];
    float st = sinf(theta);
    float ct = 1.0f - cosf(theta);
    float cf = ct / theta;
    float sf = 1.0f - st / theta;
    float R[9], V[9];
#pragma unroll
    for (int i = 0; i < 9; ++i) {
        float eye = (i == 0 || i == 4 || i == 8) ? 1.0f : 0.0f;
        R[i] = eye + st * K[i] + ct * KK[i];
        V[i] = eye + cf * K[i] + sf * KK[i];
    }
    T[0] = R[0]; T[1] = R[1]; T[2]  = R[2];
    T[3]  = V[0] * t0 + V[1] * t1 + V[2] * t2;
    T[4] = R[3]; T[5] = R[4]; T[6]  = R[5];
    T[7]  = V[3] * t0 + V[4] * t1 + V[5] * t2;
    T[8] = R[6]; T[9] = R[7]; T[10] = R[8];
    T[11] = V[6] * t0 + V[7] * t1 + V[8] * t2;
}

__device__ inline void compose12(const float A[12], const float B[12], float C[12]) {
#pragma unroll
    for (int i = 0; i < 3; ++i) {
#pragma unroll
        for (int j = 0; j < 4; ++j) {
            float s = A[i * 4 + 0] * B[0 * 4 + j]
                    + A[i * 4 + 1] * B[1 * 4 + j]
                    + A[i * 4 + 2] * B[2 * 4 + j];
            if (j == 3) s += A[i * 4 + 3];
            C[i * 4 + j] = s;
        }
    }
}

__device__ inline void build_hyp12(int m, float n0, float n1, float n2,
                                   const float* Tp, float T[12]) {
    const float DEG = 0.017453292519943295f;
    float xi[6];
    xi[0] = n0; xi[1] = n1; xi[2] = n2;
    xi[3] = 0.0f;
    xi[4] = (float)(-11 + 2 * (m / 12)) * DEG;
    xi[5] = (float)(-11 + 2 * (m % 12)) * DEG;
    float dT[12];
    se3exp12(xi, dT);
    compose12(dT, Tp, T);
}

__device__ inline void mm4(const float A[16], const float B[16], float C[16]) {
#pragma unroll
    for (int i = 0; i < 4; ++i)
#pragma unroll
        for (int j = 0; j < 4; ++j)
            C[i * 4 + j] = A[i * 4 + 0] * B[0 * 4 + j]
                         + A[i * 4 + 1] * B[1 * 4 + j]
                         + A[i * 4 + 2] * B[2 * 4 + j]
                         + A[i * 4 + 3] * B[3 * 4 + j];
}

// ===========================================================================
// Warp-strip Gram build (PPT=2, float2 loads) — identical math to R10.
// ===========================================================================
__device__ __forceinline__ void build_strip2(
        const float* __restrict__ q, const float* __restrict__ r,
        const float* __restrict__ u,
        int C, int H, int W, int offpix, int s, int lane) {
    const unsigned FULL = 0xffffffffu;
    int spr = W >> 6;
    int xt = s & (spr - 1);
    int y  = (s / spr) % H;
    int b  = s / (spr * H);
    int x  = (xt << 6) + (lane << 1);
    int yd = min(y + 1, H - 1);
    int HW = H * W;

    const float* qb = q + (size_t)b * C * HW;
    const float* rb = r + (size_t)b * C * HW;
    int o0 = y * W + x;
    int o1 = yd * W + x;
    bool fix = (lane == 31) && (((xt + 1) << 6) < W);

    float S0 = 0.f, R0 = 0.f, D0 = 0.f, G0 = 0.f, A0 = 0.f;
    float S1 = 0.f, R1 = 0.f, D1 = 0.f, G1 = 0.f, A1 = 0.f;

#pragma unroll 4
    for (int c = 0; c < C; ++c) {
        const float* qc = qb + (size_t)c * HW;
        const float* rc = rb + (size_t)c * HW;
        float2 qa = *reinterpret_cast<const float2*>(qc + o0);
        float2 ra = *reinterpret_cast<const float2*>(rc + o0);
        float2 qd = *reinterpret_cast<const float2*>(qc + o1);
        float2 rd = *reinterpret_cast<const float2*>(rc + o1);
        float da0 = qa.x - ra.x, da1 = qa.y - ra.y;
        float db0 = qd.x - rd.x, db1 = qd.y - rd.y;
        float e0 = __shfl_down_sync(FULL, da0, 1);
        float e1 = __shfl_down_sync(FULL, db0, 1);
        if (lane == 31) {
            if (fix) {
                e0 = qc[o0 + 2] - rc[o0 + 2];
                e1 = qc[o1 + 2] - rc[o1 + 2];
            } else {
                e0 = da1;
                e1 = db1;
            }
        }
        S0 = fmaf(da0, da0, S0);
        R0 = fmaf(da0, da1, R0);
        D0 = fmaf(da0, db0, D0);
        G0 = fmaf(da0, db1, G0);
        A0 = fmaf(da1, db0, A0);
        S1 = fmaf(da1, da1, S1);
        R1 = fmaf(da1, e0,  R1);
        D1 = fmaf(da1, db1, D1);
        G1 = fmaf(da1, e1,  G1);
        A1 = fmaf(e0,  db1, A1);
    }
    float Ua = u[(size_t)b * HW + o0];
    float Ub = u[(size_t)b * HW + o0 + 1];
    int pix = offpix + b * HW + o0;
    g_maps[pix * 2 + 0] = make_float4(S0, R0, D0, G0);
    g_maps[pix * 2 + 1] = make_float4(A0, Ua, 0.f, 0.f);
    g_maps[pix * 2 + 2] = make_float4(S1, R1, D1, G1);
    g_maps[pix * 2 + 3] = make_float4(A1, Ub, 0.f, 0.f);
}

// ===========================================================================
// Counter reset (runs first in every replay)
// ===========================================================================
__global__ void zero_done_kernel() {
    if (threadIdx.x < 3) g_done[threadIdx.x] = 0;
}

// ===========================================================================
// FUSED kernel: 2016 CTAs x 128 thr. Every warp builds one strip (L0 first),
// then CTAs 0..127 run the 9-iteration LM chain for their (b,m), gating each
// pyramid level on the build counters.
// ===========================================================================
__global__ __launch_bounds__(128, 8)
void fused_kernel(const float* __restrict__ T_pred,
                  const float* __restrict__ geo,
                  const float* __restrict__ Kin,
                  const float* __restrict__ q0, const float* __restrict__ r0,
                  const float* __restrict__ u0,
                  const float* __restrict__ q1, const float* __restrict__ r1,
                  const float* __restrict__ u1,
                  const float* __restrict__ q2, const float* __restrict__ r2,
                  const float* __restrict__ u2,
                  TFKeys keys) {
    int tid  = threadIdx.x;
    int wid  = tid >> 5;
    int lane = tid & 31;
    const unsigned FULL = 0xffffffffu;

    // ---------------- build: one strip per warp, L0 first -----------------
    {
        int gw = blockIdx.x * 4 + wid;
        int level;
        if (gw < ST0) {
            level = 0;
            build_strip2(q0, r0, u0, 128, 48, 64, 0, gw, lane);
        } else if (gw < ST0 + ST1) {
            level = 1;
            build_strip2(q1, r1, u1, 64, 96, 128, PX0, gw - ST0, lane);
        } else {
            level = 2;
            build_strip2(q2, r2, u2, 32, 192, 256, PX0 + PX1, gw - ST0 - ST1, lane);
        }
        __threadfence();
        __syncwarp();
        if (lane == 0) atomicAdd(&g_done[level], 1);
    }

    if (blockIdx.x >= NMEGA) return;

    // ---------------- mega: (b, m) LM chain -------------------------------
    int b = blockIdx.x >> 4;
    int m = blockIdx.x & 15;

    __shared__ float sgeo[NN * 3];
    __shared__ float snz[9][6];
    __shared__ float wsum[2][4];

    __syncthreads();   // all 4 warps done with their strips

    for (int i = tid; i < NN * 3; i += 128)
        sgeo[i] = geo[b * NN * 3 + i];
    if (wid == 1) {
        for (int t = lane; t < 54; t += 32) {
            int it = t / 6, j = t % 6;
            snz[it][j] = tf_normal(keys.ik0[it], keys.ik1[it],
                                   (unsigned)((b * MM + m) * 6 + j));
        }
    }

    // initial hypothesis (redundant per warp)
    float nz = 0.f;
    if (lane < 3)
        nz = tf_normal(keys.hk0, keys.hk1, (unsigned)(m * 3 + lane));
    float n0 = __shfl_sync(FULL, nz, 0);
    float n1 = __shfl_sync(FULL, nz, 1);
    float n2 = __shfl_sync(FULL, nz, 2);
    float T[12];
    build_hyp12(m, n0, n1, n2, &T_pred[b * 16], T);

    float k00 = Kin[b * 9 + 0], k02 = Kin[b * 9 + 2];
    float k11 = Kin[b * 9 + 4], k12 = Kin[b * 9 + 5];

    const int   LH[3]    = {48, 96, 192};
    const int   LW[3]    = {64, 128, 256};
    const int   LOFF[3]  = {0, PX0, PX0 + PX1};
    const float LSC[3]   = {0.25f, 0.5f, 1.0f};
    const float LDAMP[3] = {0.001f, 0.0005f, 0.00025f};

    __syncthreads();   // sgeo/snz ready

    float res = 0.f;
    for (int it = 0; it < 9; ++it) {
        int level = (it < 2) ? 0 : ((it < 5) ? 1 : 2);

        // gate on map availability at level transitions
        if (it == 0 || it == 2 || it == 5) {
            int need = (level == 0) ? ST0 : ((level == 1) ? ST1 : ST2);
            if (tid == 0) {
                while (*((volatile int*)&g_done[level]) < need) __nanosleep(64);
                __threadfence();
            }
            __syncthreads();
        }

        int H = LH[level], W = LW[level];
        float sc = LSC[level];
        float fx = k00 * sc, fy = k11 * sc;
        float cx = k02 * sc, cy = k12 * sc;
        const float4* mp = g_maps + (size_t)LOFF[level] * 2;

        float acc = 0.f;
        for (int k = 0; k < 4; ++k) {
            int p = tid + k * 128;
            if (p < NN) {
                float X = sgeo[p * 3], Y = sgeo[p * 3 + 1], Z = sgeo[p * 3 + 2];
                float pcx = T[0] * X + T[1] * Y + T[2]  * Z + T[3];
                float pcy = T[4] * X + T[5] * Y + T[6]  * Z + T[7];
                float pcz = T[8] * X + T[9] * Y + T[10] * Z + T[11];
                float z = fmaxf(pcz, 1e-6f);
                float uu = fx * (pcx / z) + cx;
                float vv = fy * (pcy / z) + cy;
                float gx = 2.0f * uu / (float)(W - 1) - 1.0f;
                float gy = 2.0f * vv / (float)(H - 1) - 1.0f;
                float xs = ((gx + 1.0f) * (float)W - 1.0f) * 0.5f;
                float ys = ((gy + 1.0f) * (float)H - 1.0f) * 0.5f;
                xs = fminf(fmaxf(xs, 0.0f), (float)(W - 1));
                ys = fminf(fmaxf(ys, 0.0f), (float)(H - 1));
                float fx0 = floorf(xs), fy0 = floorf(ys);
                float wx = xs - fx0, wy = ys - fy0;
                int x0 = (int)fx0, y0 = (int)fy0;
                int x1 = min(x0 + 1, W - 1);
                int y1 = min(y0 + 1, H - 1);
                int rowb = (b * H + y0) * W;
                int rowd = (b * H + y1) * W;
                int i00 = (rowb + x0) * 2, i01 = (rowb + x1) * 2;
                int i10 = (rowd + x0) * 2, i11 = (rowd + x1) * 2;
                float4 a00 = mp[i00], b00 = mp[i00 + 1];
                float4 a01 = mp[i01], b01 = mp[i01 + 1];
                float4 a10 = mp[i10], b10 = mp[i10 + 1];
                float4 a11 = mp[i11], b11 = mp[i11 + 1];
                float w00 = (1.f - wx) * (1.f - wy);
                float w01 = wx * (1.f - wy);
                float w10 = (1.f - wx) * wy;
                float w11 = wx * wy;
                float qrs = w00 * w00 * a00.x + w01 * w01 * a01.x
                          + w10 * w10 * a10.x + w11 * w11 * a11.x
                          + 2.f * (w00 * w01 * a00.y + w10 * w11 * a10.y
                                 + w00 * w10 * a00.z + w01 * w11 * a01.z
                                 + w00 * w11 * a00.w + w01 * w10 * b00.x);
                float un = w00 * b00.y + w01 * b01.y + w10 * b10.y + w11 * b11.y;
                acc += qrs * un;
            }
        }
        acc += __shfl_xor_sync(FULL, acc, 16);
        acc += __shfl_xor_sync(FULL, acc, 8);
        acc += __shfl_xor_sync(FULL, acc, 4);
        acc += __shfl_xor_sync(FULL, acc, 2);
        acc += __shfl_xor_sync(FULL, acc, 1);
        if (lane == 0) wsum[it & 1][wid] = acc;
        __syncthreads();

        // redundant update in all threads (fixed order -> deterministic)
        float rsum = wsum[it & 1][0] + wsum[it & 1][1]
                   + wsum[it & 1][2] + wsum[it & 1][3];
        res = rsum / 500.0f;

        float nd = -LDAMP[level] * res * 0.01f;
        float stp[6];
#pragma unroll
        for (int j = 0; j < 6; ++j) stp[j] = nd * snz[it][j];
        float dT[12], Tn[12];
        se3exp12(stp, dT);
        compose12(dT, T, Tn);
#pragma unroll
        for (int k = 0; k < 12; ++k) T[k] = Tn[k];
    }

    if (tid == 0) {
        g_costs[b * M16 + m] = res;
#pragma unroll
        for (int k = 0; k < 12; ++k)
            g_Tcur[(b * M16 + m) * 12 + k] = T[k];
    }
}

// ===========================================================================
// Kernel 3: finalize — geodesic + argmin + outputs
// ===========================================================================
__global__ __launch_bounds__(256)
void finalize_kernel(const float* __restrict__ T_pred,
                     float* __restrict__ out, TFKeys keys) {
    int b = blockIdx.x;
    int tid = threadIdx.x;
    int m = tid;
    __shared__ float sv[256];
    __shared__ int si[256];

    const float* Tp = &T_pred[b * 16];
    float T[16];
#pragma unroll
    for (int k = 0; k < 16; ++k) T[k] = 0.f;
    T[15] = 1.f;
    float cost = 0.f;
    float total = 3.0e38f;

    if (m < MM) {
        if (m < M16) {
#pragma unroll
            for (int k = 0; k < 12; ++k) T[k] = g_Tcur[(b * M16 + m) * 12 + k];
            cost = g_costs[b * M16 + m];
        } else {
            float n0 = tf_normal(keys.hk0, keys.hk1, (unsigned)(m * 3 + 0));
            float n1 = tf_normal(keys.hk0, keys.hk1, (unsigned)(m * 3 + 1));
            float n2 = tf_normal(keys.hk0, keys.hk1, (unsigned)(m * 3 + 2));
            float T12[12];
            build_hyp12(m, n0, n1, n2, Tp, T12);
#pragma unroll
            for (int k = 0; k < 12; ++k) T[k] = T12[k];
        }
        float Ti[16];
        Ti[0] = Tp[0]; Ti[1] = Tp[4]; Ti[2]  = Tp[8];
        Ti[4] = Tp[1]; Ti[5] = Tp[5]; Ti[6]  = Tp[9];
        Ti[8] = Tp[2]; Ti[9] = Tp[6]; Ti[10] = Tp[10];
        Ti[3]  = -(Ti[0] * Tp[3] + Ti[1] * Tp[7] + Ti[2]  * Tp[11]);
        Ti[7]  = -(Ti[4] * Tp[3] + Ti[5] * Tp[7] + Ti[6]  * Tp[11]);
        Ti[11] = -(Ti[8] * Tp[3] + Ti[9] * Tp[7] + Ti[10] * Tp[11]);
        Ti[12] = 0.f; Ti[13] = 0.f; Ti[14] = 0.f; Ti[15] = 1.f;

        float Tr[16];
        mm4(T, Ti, Tr);

        float tr = Tr[0] + Tr[5] + Tr[10];
        float ca = (tr - 1.0f) * 0.5f;
        ca = fminf(fmaxf(ca, -1.0f + 1e-7f), 1.0f - 1e-7f);
        float theta = acosf(ca);
        float th = fmaxf(theta, 1e-8f);
        float sn = fmaxf(sinf(th), 1e-8f);
        float fac = th / (2.0f * sn);
        float w0 = (Tr[9] - Tr[6]) * fac;
        float w1 = (Tr[2] - Tr[8]) * fac;
        float w2 = (Tr[4] - Tr[1]) * fac;
        if (fabsf(theta) < 1e-6f) { w0 = 0.f; w1 = 0.f; w2 = 0.f; }
        float t0 = Tr[3], t1 = Tr[7], t2 = Tr[11];
        float geod = sqrtf(t0 * t0 + t1 * t1 + t2 * t2
                         + w0 * w0 + w1 * w1 + w2 * w2);
        total = cost + geod;
    }

    sv[tid] = total;
    si[tid] = tid;
    __syncthreads();
    for (int s = 128; s > 0; s >>= 1) {
        if (tid < s) {
            if (sv[tid + s] < sv[tid]) {
                sv[tid] = sv[tid + s];
                si[tid] = si[tid + s];
            }
        }
        __syncthreads();
    }
    int best = si[0];

    if (m == best) {
#pragma unroll
        for (int k = 0; k < 16; ++k) out[b * 16 + k] = T[k];
    }
    if (m < MM) out[BB * 16 + b * MM + m] = cost;
}

// ===========================================================================
// Launch (single stream)
// ===========================================================================
extern "C" void kernel_launch(void* const* d_in, const int* in_sizes, int n_in,
                              void* d_out, int out_size) {
    (void)in_sizes; (void)n_in; (void)out_size;
    const float* T_pred = (const float*)d_in[0];
    const float* geo    = (const float*)d_in[1];
    const float* K      = (const float*)d_in[2];
    const float* q0 = (const float*)d_in[3];
    const float* q1 = (const float*)d_in[4];
    const float* q2 = (const float*)d_in[5];
    const float* r0 = (const float*)d_in[6];
    const float* r1 = (const float*)d_in[7];
    const float* r2 = (const float*)d_in[8];
    const float* u0 = (const float*)d_in[9];
    const float* u1 = (const float*)d_in[10];
    const float* u2 = (const float*)d_in[11];
    float* out = (float*)d_out;

    TFKeys keys;
    {
        unsigned x0 = 0, x1 = 0;
        tf2x32(0u, 42u, x0, x1);
        keys.hk0 = x0; keys.hk1 = x1;
        const unsigned ds[9] = {100u, 101u, 110u, 111u, 112u,
                                120u, 121u, 122u, 123u};
        for (int i = 0; i < 9; ++i) {
            unsigned a = 0, bb2 = ds[i];
            tf2x32(0u, 42u, a, bb2);
            keys.ik0[i] = a; keys.ik1[i] = bb2;
        }
    }

    zero_done_kernel<<<1, 32>>>();
    fused_kernel<<<NCTAS, 128>>>(T_pred, geo, K,
                                 q0, r0, u0, q1, r1, u1, q2, r2, u2, keys);
    finalize_kernel<<<BB, 256>>>(T_pred, out, keys);
}

// round 14
// speedup vs baseline: 1.3312x; 1.3312x over previous
#include <cuda_runtime.h>
#include <math.h>

// ===========================================================================
// Problem constants
// ===========================================================================
#define BB 8
#define MM 144
#define M16 16
#define NN 500

// L0: C=128 H=48 W=64 | L1: C=64 H=96 W=128 | L2: C=32 H=192 W=256
#define PX0 (8*48*64)     /* 24576  */
#define PX1 (8*96*128)    /* 98304  */
#define PX2 (8*192*256)   /* 393216 */

// strips: PPT=2 everywhere -> warp covers 64 consecutive x; 4 warps per CTA
#define ST0 (8*48)        /* 384  */
#define ST1 (8*96*2)      /* 1536 */
#define ST2 (8*192*4)     /* 6144 */
#define NSTRIPS (ST0+ST1+ST2)   /* 8064 */
#define NCTAS (NSTRIPS/4)       /* 2016 */

// Gram/unc maps: per pixel a 32B record {S,R,D,G | A,U,0,0} as two float4
__device__ float4 g_maps[(PX0 + PX1 + PX2) * 2];
__device__ float  g_Tcur[BB * M16 * 12];
__device__ float  g_costs[BB * M16];

// ===========================================================================
// Threefry2x32 (JAX-compatible, 20 rounds)
// ===========================================================================
__host__ __device__ inline void tf2x32(unsigned k0, unsigned k1,
                                       unsigned& x0, unsigned& x1) {
    unsigned ks2 = k0 ^ k1 ^ 0x1BD11BDAu;
    x0 += k0; x1 += k1;
#define TF_RND(r) { x0 += x1; x1 = (x1 << (r)) | (x1 >> (32 - (r))); x1 ^= x0; }
    TF_RND(13) TF_RND(15) TF_RND(26) TF_RND(6)
    x0 += k1; x1 += ks2 + 1u;
    TF_RND(17) TF_RND(29) TF_RND(16) TF_RND(24)
    x0 += ks2; x1 += k0 + 2u;
    TF_RND(13) TF_RND(15) TF_RND(26) TF_RND(6)
    x0 += k0; x1 += k1 + 3u;
    TF_RND(17) TF_RND(29) TF_RND(16) TF_RND(24)
    x0 += k1; x1 += ks2 + 4u;
    TF_RND(13) TF_RND(15) TF_RND(26) TF_RND(6)
    x0 += ks2; x1 += k0 + 5u;
#undef TF_RND
}

struct TFKeys {
    unsigned hk0, hk1;
    unsigned ik0[9], ik1[9];
};

// XLA ErfInv (float32, Giles polynomial)
__device__ inline float erfinv_x(float x) {
    float w = -log1pf(-x * x);
    float p;
    if (w < 5.0f) {
        w = w - 2.5f;
        p = 2.81022636e-08f;
        p = fmaf(p, w, 3.43273939e-07f);
        p = fmaf(p, w, -3.5233877e-06f);
        p = fmaf(p, w, -4.39150654e-06f);
        p = fmaf(p, w, 0.00021858087f);
        p = fmaf(p, w, -0.00125372503f);
        p = fmaf(p, w, -0.00417768164f);
        p = fmaf(p, w, 0.246640727f);
        p = fmaf(p, w, 1.50140941f);
    } else {
        w = sqrtf(w) - 3.0f;
        p = -0.000200214257f;
        p = fmaf(p, w, 0.000100950558f);
        p = fmaf(p, w, 0.00134934322f);
        p = fmaf(p, w, -0.00367342844f);
        p = fmaf(p, w, 0.00573950773f);
        p = fmaf(p, w, -0.0076224613f);
        p = fmaf(p, w, 0.00943887047f);
        p = fmaf(p, w, 1.00167406f);
        p = fmaf(p, w, 2.83297682f);
    }
    return p * x;
}

// jax.random.normal, partitionable threefry: bits[i] = x0 ^ x1 of enc(key,(0,i))
__device__ inline float tf_normal(unsigned k0, unsigned k1, unsigned idx) {
    unsigned x0 = 0u, x1 = idx;
    tf2x32(k0, k1, x0, x1);
    unsigned bits = x0 ^ x1;
    float f = __uint_as_float((bits >> 9) | 0x3f800000u) - 1.0f;
    const float lo = -0.99999994f;
    float u = fmaxf(lo, f * 2.0f + lo);
    return 1.4142135623730951f * erfinv_x(u);
}

// ===========================================================================
// SE(3) helpers — affine 3x4 (12-float)
// ===========================================================================
__device__ inline void se3exp12(const float xi[6], float T[12]) {
    float t0 = xi[0], t1 = xi[1], t2 = xi[2];
    float w0 = xi[3], w1 = xi[4], w2 = xi[5];
    float nw = sqrtf(w0 * w0 + w1 * w1 + w2 * w2);
    float theta = fmaxf(nw, 1e-8f);
    float a0 = w0 / theta, a1 = w1 / theta, a2 = w2 / theta;
    float K[9] = { 0.f, -a2,  a1,
                   a2,  0.f, -a0,
                  -a1,  a0,  0.f };
    float KK[9];
#pragma unroll
    for (int i = 0; i < 3; ++i)
#pragma unroll
        for (int j = 0; j < 3; ++j)
            KK[i * 3 + j] = K[i * 3 + 0] * K[0 * 3 + j]
                          + K[i * 3 + 1] * K[1 * 3 + j]
                          + K[i * 3 + 2] * K[2 * 3 + j];
    float st = sinf(theta);
    float ct = 1.0f - cosf(theta);
    float cf = ct / theta;
    float sf = 1.0f - st / theta;
    float R[9], V[9];
#pragma unroll
    for (int i = 0; i < 9; ++i) {
        float eye = (i == 0 || i == 4 || i == 8) ? 1.0f : 0.0f;
        R[i] = eye + st * K[i] + ct * KK[i];
        V[i] = eye + cf * K[i] + sf * KK[i];
    }
    T[0] = R[0]; T[1] = R[1]; T[2]  = R[2];
    T[3]  = V[0] * t0 + V[1] * t1 + V[2] * t2;
    T[4] = R[3]; T[5] = R[4]; T[6]  = R[5];
    T[7]  = V[3] * t0 + V[4] * t1 + V[5] * t2;
    T[8] = R[6]; T[9] = R[7]; T[10] = R[8];
    T[11] = V[6] * t0 + V[7] * t1 + V[8] * t2;
}

__device__ inline void compose12(const float A[12], const float B[12], float C[12]) {
#pragma unroll
    for (int i = 0; i < 3; ++i) {
#pragma unroll
        for (int j = 0; j < 4; ++j) {
            float s = A[i * 4 + 0] * B[0 * 4 + j]
                    + A[i * 4 + 1] * B[1 * 4 + j]
                    + A[i * 4 + 2] * B[2 * 4 + j];
            if (j == 3) s += A[i * 4 + 3];
            C[i * 4 + j] = s;
        }
    }
}

__device__ inline void build_hyp12(int m, float n0, float n1, float n2,
                                   const float* Tp, float T[12]) {
    const float DEG = 0.017453292519943295f;
    float xi[6];
    xi[0] = n0; xi[1] = n1; xi[2] = n2;
    xi[3] = 0.0f;
    xi[4] = (float)(-11 + 2 * (m / 12)) * DEG;
    xi[5] = (float)(-11 + 2 * (m % 12)) * DEG;
    float dT[12];
    se3exp12(xi, dT);
    compose12(dT, Tp, T);
}

__device__ inline void mm4(const float A[16], const float B[16], float C[16]) {
#pragma unroll
    for (int i = 0; i < 4; ++i)
#pragma unroll
        for (int j = 0; j < 4; ++j)
            C[i * 4 + j] = A[i * 4 + 0] * B[0 * 4 + j]
                         + A[i * 4 + 1] * B[1 * 4 + j]
                         + A[i * 4 + 2] * B[2 * 4 + j]
                         + A[i * 4 + 3] * B[3 * 4 + j];
}

// ===========================================================================
// Kernel 1: vectorized warp-strip Gram build (PPT=2, float2 loads).
// unroll 8 + launch_bounds(128,9): ~2x outstanding loads per warp at
// near-equal occupancy -> higher achieved DRAM bandwidth.
// ===========================================================================
__device__ __forceinline__ void build_strip2(
        const float* __restrict__ q, const float* __restrict__ r,
        const float* __restrict__ u,
        int C, int H, int W, int offpix, int s, int lane) {
    const unsigned FULL = 0xffffffffu;
    int spr = W >> 6;                    // strips per row (W/64)
    int xt = s & (spr - 1);
    int y  = (s / spr) % H;
    int b  = s / (spr * H);
    int x  = (xt << 6) + (lane << 1);
    int yd = min(y + 1, H - 1);
    int HW = H * W;

    const float* qb = q + (size_t)b * C * HW;
    const float* rb = r + (size_t)b * C * HW;
    int o0 = y * W + x;
    int o1 = yd * W + x;
    bool fix = (lane == 31) && (((xt + 1) << 6) < W);

    float S0 = 0.f, R0 = 0.f, D0 = 0.f, G0 = 0.f, A0 = 0.f;
    float S1 = 0.f, R1 = 0.f, D1 = 0.f, G1 = 0.f, A1 = 0.f;

#pragma unroll 8
    for (int c = 0; c < C; ++c) {
        const float* qc = qb + (size_t)c * HW;
        const float* rc = rb + (size_t)c * HW;
        float2 qa = *reinterpret_cast<const float2*>(qc + o0);
        float2 ra = *reinterpret_cast<const float2*>(rc + o0);
        float2 qd = *reinterpret_cast<const float2*>(qc + o1);
        float2 rd = *reinterpret_cast<const float2*>(rc + o1);
        float da0 = qa.x - ra.x, da1 = qa.y - ra.y;   // row y, px x, x+1
        float db0 = qd.x - rd.x, db1 = qd.y - rd.y;   // row y+1
        float e0 = __shfl_down_sync(FULL, da0, 1);
        float e1 = __shfl_down_sync(FULL, db0, 1);
        if (lane == 31) {
            if (fix) {
                e0 = qc[o0 + 2] - rc[o0 + 2];
                e1 = qc[o1 + 2] - rc[o1 + 2];
            } else {         // x+1==W-1 at image edge: clamp -> own last px
                e0 = da1;
                e1 = db1;
            }
        }
        S0 = fmaf(da0, da0, S0);
        R0 = fmaf(da0, da1, R0);
        D0 = fmaf(da0, db0, D0);
        G0 = fmaf(da0, db1, G0);
        A0 = fmaf(da1, db0, A0);
        S1 = fmaf(da1, da1, S1);
        R1 = fmaf(da1, e0,  R1);
        D1 = fmaf(da1, db1, D1);
        G1 = fmaf(da1, e1,  G1);
        A1 = fmaf(e0,  db1, A1);
    }
    float Ua = u[(size_t)b * HW + o0];
    float Ub = u[(size_t)b * HW + o0 + 1];
    int pix = offpix + b * HW + o0;
    g_maps[pix * 2 + 0] = make_float4(S0, R0, D0, G0);
    g_maps[pix * 2 + 1] = make_float4(A0, Ua, 0.f, 0.f);
    g_maps[pix * 2 + 2] = make_float4(S1, R1, D1, G1);
    g_maps[pix * 2 + 3] = make_float4(A1, Ub, 0.f, 0.f);
}

__global__ __launch_bounds__(128, 9)
void build_all_kernel(const float* __restrict__ q0, const float* __restrict__ r0,
                      const float* __restrict__ u0,
                      const float* __restrict__ q1, const float* __restrict__ r1,
                      const float* __restrict__ u1,
                      const float* __restrict__ q2, const float* __restrict__ r2,
                      const float* __restrict__ u2) {
    int wid  = threadIdx.x >> 5;
    int lane = threadIdx.x & 31;
    int gw = blockIdx.x * 4 + wid;
    if (gw < ST0) {
        build_strip2(q0, r0, u0, 128, 48, 64, 0, gw, lane);
    } else if (gw < ST0 + ST1) {
        build_strip2(q1, r1, u1, 64, 96, 128, PX0, gw - ST0, lane);
    } else {
        build_strip2(q2, r2, u2, 32, 192, 256, PX0 + PX1, gw - ST0 - ST1, lane);
    }
}

// ===========================================================================
// Kernel 2: mega kernel — one CTA (512 thr) per (b, m<16); 9 LM iterations.
// Register-resident pose, redundant update, 1 barrier/iter, precomputed noise.
// ===========================================================================
__global__ __launch_bounds__(512)
void mega_kernel(const float* __restrict__ T_pred,
                 const float* __restrict__ geo,
                 const float* __restrict__ Kin,
                 TFKeys keys) {
    int bm = blockIdx.x;
    int b = bm >> 4;
    int m = bm & 15;
    int tid  = threadIdx.x;
    int wid  = tid >> 5;
    int lane = tid & 31;
    const unsigned FULL = 0xffffffffu;

    __shared__ float wsum[2][16];
    __shared__ float snz[9][6];

    // precompute all 54 iteration-noise values (warp 1, off critical path)
    if (wid == 1) {
        unsigned base = (unsigned)((b * MM + m) * 6);
        if (lane < 54) {
            int it = lane / 6, j = lane % 6;
            snz[it][j] = tf_normal(keys.ik0[it], keys.ik1[it], base + (unsigned)j);
        }
        if (lane + 32 < 54) {
            int l2 = lane + 32;
            int it = l2 / 6, j = l2 % 6;
            snz[it][j] = tf_normal(keys.ik0[it], keys.ik1[it], base + (unsigned)j);
        }
    }

    // initial hypothesis (redundant per warp)
    float nz = 0.f;
    if (lane < 3)
        nz = tf_normal(keys.hk0, keys.hk1, (unsigned)(m * 3 + lane));
    float n0 = __shfl_sync(FULL, nz, 0);
    float n1 = __shfl_sync(FULL, nz, 1);
    float n2 = __shfl_sync(FULL, nz, 2);
    float T[12];
    build_hyp12(m, n0, n1, n2, &T_pred[b * 16], T);

    bool act = tid < NN;
    float X = 0.f, Y = 0.f, Z = 0.f;
    if (act) {
        const float* gp = &geo[(b * NN + tid) * 3];
        X = gp[0]; Y = gp[1]; Z = gp[2];
    }
    float k00 = Kin[b * 9 + 0], k02 = Kin[b * 9 + 2];
    float k11 = Kin[b * 9 + 4], k12 = Kin[b * 9 + 5];

    const int   LH[3]    = {48, 96, 192};
    const int   LW[3]    = {64, 128, 256};
    const int   LOFF[3]  = {0, PX0, PX0 + PX1};
    const float LSC[3]   = {0.25f, 0.5f, 1.0f};
    const float LDAMP[3] = {0.001f, 0.0005f, 0.00025f};

    __syncthreads();   // snz ready

    float res = 0.f;
    for (int it = 0; it < 9; ++it) {
        int level = (it < 2) ? 0 : ((it < 5) ? 1 : 2);
        int H = LH[level], W = LW[level];
        float sc = LSC[level];
        float fx = k00 * sc, fy = k11 * sc;
        float cx = k02 * sc, cy = k12 * sc;
        const float4* mp = g_maps + (size_t)LOFF[level] * 2;

        float acc = 0.f;
        if (act) {
            float pcx = T[0] * X + T[1] * Y + T[2]  * Z + T[3];
            float pcy = T[4] * X + T[5] * Y + T[6]  * Z + T[7];
            float pcz = T[8] * X + T[9] * Y + T[10] * Z + T[11];
            float z = fmaxf(pcz, 1e-6f);
            float uu = fx * (pcx / z) + cx;
            float vv = fy * (pcy / z) + cy;
            float gx = 2.0f * uu / (float)(W - 1) - 1.0f;
            float gy = 2.0f * vv / (float)(H - 1) - 1.0f;
            float xs = ((gx + 1.0f) * (float)W - 1.0f) * 0.5f;
            float ys = ((gy + 1.0f) * (float)H - 1.0f) * 0.5f;
            xs = fminf(fmaxf(xs, 0.0f), (float)(W - 1));
            ys = fminf(fmaxf(ys, 0.0f), (float)(H - 1));
            float fx0 = floorf(xs), fy0 = floorf(ys);
            float wx = xs - fx0, wy = ys - fy0;
            int x0 = (int)fx0, y0 = (int)fy0;
            int x1 = min(x0 + 1, W - 1);
            int y1 = min(y0 + 1, H - 1);
            int rowb = (b * H + y0) * W;
            int rowd = (b * H + y1) * W;
            int i00 = (rowb + x0) * 2, i01 = (rowb + x1) * 2;
            int i10 = (rowd + x0) * 2, i11 = (rowd + x1) * 2;
            float4 a00 = mp[i00], b00 = mp[i00 + 1];
            float4 a01 = mp[i01], b01 = mp[i01 + 1];
            float4 a10 = mp[i10], b10 = mp[i10 + 1];
            float4 a11 = mp[i11], b11 = mp[i11 + 1];
            float w00 = (1.f - wx) * (1.f - wy);
            float w01 = wx * (1.f - wy);
            float w10 = (1.f - wx) * wy;
            float w11 = wx * wy;
            float qrs = w00 * w00 * a00.x + w01 * w01 * a01.x
                      + w10 * w10 * a10.x + w11 * w11 * a11.x
                      + 2.f * (w00 * w01 * a00.y + w10 * w11 * a10.y
                             + w00 * w10 * a00.z + w01 * w11 * a01.z
                             + w00 * w11 * a00.w + w01 * w10 * b00.x);
            float un = w00 * b00.y + w01 * b01.y + w10 * b10.y + w11 * b11.y;
            acc = qrs * un;
        }
        acc += __shfl_xor_sync(FULL, acc, 16);
        acc += __shfl_xor_sync(FULL, acc, 8);
        acc += __shfl_xor_sync(FULL, acc, 4);
        acc += __shfl_xor_sync(FULL, acc, 2);
        acc += __shfl_xor_sync(FULL, acc, 1);
        if (lane == 0) wsum[it & 1][wid] = acc;
        __syncthreads();

        // redundant update in ALL threads (identical result, no 2nd barrier)
        float rsum = 0.f;
#pragma unroll
        for (int w = 0; w < 16; ++w) rsum += wsum[it & 1][w];
        res = rsum / 500.0f;

        float nd = -LDAMP[level] * res * 0.01f;
        float stp[6];
#pragma unroll
        for (int j = 0; j < 6; ++j) stp[j] = nd * snz[it][j];
        float dT[12], Tn[12];
        se3exp12(stp, dT);
        compose12(dT, T, Tn);
#pragma unroll
        for (int k = 0; k < 12; ++k) T[k] = Tn[k];
    }

    if (tid == 0) {
        g_costs[b * M16 + m] = res;
#pragma unroll
        for (int k = 0; k < 12; ++k)
            g_Tcur[(b * M16 + m) * 12 + k] = T[k];
    }
}

// ===========================================================================
// Kernel 3: finalize — geodesic + argmin + outputs
// ===========================================================================
__global__ __launch_bounds__(256)
void finalize_kernel(const float* __restrict__ T_pred,
                     float* __restrict__ out, TFKeys keys) {
    int b = blockIdx.x;
    int tid = threadIdx.x;
    int m = tid;
    __shared__ float sv[256];
    __shared__ int si[256];

    const float* Tp = &T_pred[b * 16];
    float T[16];
#pragma unroll
    for (int k = 0; k < 16; ++k) T[k] = 0.f;
    T[15] = 1.f;
    float cost = 0.f;
    float total = 3.0e38f;

    if (m < MM) {
        if (m < M16) {
#pragma unroll
            for (int k = 0; k < 12; ++k) T[k] = g_Tcur[(b * M16 + m) * 12 + k];
            cost = g_costs[b * M16 + m];
        } else {
            float n0 = tf_normal(keys.hk0, keys.hk1, (unsigned)(m * 3 + 0));
            float n1 = tf_normal(keys.hk0, keys.hk1, (unsigned)(m * 3 + 1));
            float n2 = tf_normal(keys.hk0, keys.hk1, (unsigned)(m * 3 + 2));
            float T12[12];
            build_hyp12(m, n0, n1, n2, Tp, T12);
#pragma unroll
            for (int k = 0; k < 12; ++k) T[k] = T12[k];
        }
        float Ti[16];
        Ti[0] = Tp[0]; Ti[1] = Tp[4]; Ti[2]  = Tp[8];
        Ti[4] = Tp[1]; Ti[5] = Tp[5]; Ti[6]  = Tp[9];
        Ti[8] = Tp[2]; Ti[9] = Tp[6]; Ti[10] = Tp[10];
        Ti[3]  = -(Ti[0] * Tp[3] + Ti[1] * Tp[7] + Ti[2]  * Tp[11]);
        Ti[7]  = -(Ti[4] * Tp[3] + Ti[5] * Tp[7] + Ti[6]  * Tp[11]);
        Ti[11] = -(Ti[8] * Tp[3] + Ti[9] * Tp[7] + Ti[10] * Tp[11]);
        Ti[12] = 0.f; Ti[13] = 0.f; Ti[14] = 0.f; Ti[15] = 1.f;

        float Tr[16];
        mm4(T, Ti, Tr);

        float tr = Tr[0] + Tr[5] + Tr[10];
        float ca = (tr - 1.0f) * 0.5f;
        ca = fminf(fmaxf(ca, -1.0f + 1e-7f), 1.0f - 1e-7f);
        float theta = acosf(ca);
        float th = fmaxf(theta, 1e-8f);
        float sn = fmaxf(sinf(th), 1e-8f);
        float fac = th / (2.0f * sn);
        float w0 = (Tr[9] - Tr[6]) * fac;
        float w1 = (Tr[2] - Tr[8]) * fac;
        float w2 = (Tr[4] - Tr[1]) * fac;
        if (fabsf(theta) < 1e-6f) { w0 = 0.f; w1 = 0.f; w2 = 0.f; }
        float t0 = Tr[3], t1 = Tr[7], t2 = Tr[11];
        float geod = sqrtf(t0 * t0 + t1 * t1 + t2 * t2
                         + w0 * w0 + w1 * w1 + w2 * w2);
        total = cost + geod;
    }

    sv[tid] = total;
    si[tid] = tid;
    __syncthreads();
    for (int s = 128; s > 0; s >>= 1) {
        if (tid < s) {
            if (sv[tid + s] < sv[tid]) {
                sv[tid] = sv[tid + s];
                si[tid] = si[tid + s];
            }
        }
        __syncthreads();
    }
    int best = si[0];

    if (m == best) {
#pragma unroll
        for (int k = 0; k < 16; ++k) out[b * 16 + k] = T[k];
    }
    if (m < MM) out[BB * 16 + b * MM + m] = cost;
}

// ===========================================================================
// Launch (single stream, sequential — proven path)
// ===========================================================================
extern "C" void kernel_launch(void* const* d_in, const int* in_sizes, int n_in,
                              void* d_out, int out_size) {
    (void)in_sizes; (void)n_in; (void)out_size;
    const float* T_pred = (const float*)d_in[0];
    const float* geo    = (const float*)d_in[1];
    const float* K      = (const float*)d_in[2];
    const float* q0 = (const float*)d_in[3];
    const float* q1 = (const float*)d_in[4];
    const float* q2 = (const float*)d_in[5];
    const float* r0 = (const float*)d_in[6];
    const float* r1 = (const float*)d_in[7];
    const float* r2 = (const float*)d_in[8];
    const float* u0 = (const float*)d_in[9];
    const float* u1 = (const float*)d_in[10];
    const float* u2 = (const float*)d_in[11];
    float* out = (float*)d_out;

    TFKeys keys;
    {
        unsigned x0 = 0, x1 = 0;
        tf2x32(0u, 42u, x0, x1);
        keys.hk0 = x0; keys.hk1 = x1;
        const unsigned ds[9] = {100u, 101u, 110u, 111u, 112u,
                                120u, 121u, 122u, 123u};
        for (int i = 0; i < 9; ++i) {
            unsigned a = 0, bb2 = ds[i];
            tf2x32(0u, 42u, a, bb2);
            keys.ik0[i] = a; keys.ik1[i] = bb2;
        }
    }

    build_all_kernel<<<NCTAS, 128>>>(q0, r0, u0, q1, r1, u1, q2, r2, u2);
    mega_kernel<<<BB * M16, 512>>>(T_pred, geo, K, keys);
    finalize_kernel<<<BB, 256>>>(T_pred, out, keys);
}

// round 15
// speedup vs baseline: 1.4110x; 1.0599x over previous
#include <cuda_runtime.h>
#include <math.h>

// ===========================================================================
// Problem constants
// ===========================================================================
#define BB 8
#define MM 144
#define M16 16
#define NN 500

// L0: C=128 H=48 W=64 | L1: C=64 H=96 W=128 | L2: C=32 H=192 W=256
#define PX0 (8*48*64)     /* 24576  */
#define PX1 (8*96*128)    /* 98304  */
#define PX2 (8*192*256)   /* 393216 */

// strips: PPT=2 everywhere -> warp covers 64 consecutive x; 4 warps per CTA
#define ST0 (8*48)        /* 384  */
#define ST1 (8*96*2)      /* 1536 */
#define ST2 (8*192*4)     /* 6144 */
#define NSTRIPS (ST0+ST1+ST2)   /* 8064 */
#define NCTAS (NSTRIPS/4)       /* 2016 */

// Gram/unc maps: per pixel a 32B record {S,R,D,G | A,U,0,0} as two float4
__device__ float4 g_maps[(PX0 + PX1 + PX2) * 2];
__device__ float  g_Tcur[BB * M16 * 12];
__device__ float  g_costs[BB * M16];

// ===========================================================================
// Threefry2x32 (JAX-compatible, 20 rounds)
// ===========================================================================
__host__ __device__ inline void tf2x32(unsigned k0, unsigned k1,
                                       unsigned& x0, unsigned& x1) {
    unsigned ks2 = k0 ^ k1 ^ 0x1BD11BDAu;
    x0 += k0; x1 += k1;
#define TF_RND(r) { x0 += x1; x1 = (x1 << (r)) | (x1 >> (32 - (r))); x1 ^= x0; }
    TF_RND(13) TF_RND(15) TF_RND(26) TF_RND(6)
    x0 += k1; x1 += ks2 + 1u;
    TF_RND(17) TF_RND(29) TF_RND(16) TF_RND(24)
    x0 += ks2; x1 += k0 + 2u;
    TF_RND(13) TF_RND(15) TF_RND(26) TF_RND(6)
    x0 += k0; x1 += k1 + 3u;
    TF_RND(17) TF_RND(29) TF_RND(16) TF_RND(24)
    x0 += k1; x1 += ks2 + 4u;
    TF_RND(13) TF_RND(15) TF_RND(26) TF_RND(6)
    x0 += ks2; x1 += k0 + 5u;
#undef TF_RND
}

struct TFKeys {
    unsigned hk0, hk1;
    unsigned ik0[9], ik1[9];
};

// XLA ErfInv (float32, Giles polynomial)
__device__ inline float erfinv_x(float x) {
    float w = -log1pf(-x * x);
    float p;
    if (w < 5.0f) {
        w = w - 2.5f;
        p = 2.81022636e-08f;
        p = fmaf(p, w, 3.43273939e-07f);
        p = fmaf(p, w, -3.5233877e-06f);
        p = fmaf(p, w, -4.39150654e-06f);
        p = fmaf(p, w, 0.00021858087f);
        p = fmaf(p, w, -0.00125372503f);
        p = fmaf(p, w, -0.00417768164f);
        p = fmaf(p, w, 0.246640727f);
        p = fmaf(p, w, 1.50140941f);
    } else {
        w = sqrtf(w) - 3.0f;
        p = -0.000200214257f;
        p = fmaf(p, w, 0.000100950558f);
        p = fmaf(p, w, 0.00134934322f);
        p = fmaf(p, w, -0.00367342844f);
        p = fmaf(p, w, 0.00573950773f);
        p = fmaf(p, w, -0.0076224613f);
        p = fmaf(p, w, 0.00943887047f);
        p = fmaf(p, w, 1.00167406f);
        p = fmaf(p, w, 2.83297682f);
    }
    return p * x;
}

// jax.random.normal, partitionable threefry: bits[i] = x0 ^ x1 of enc(key,(0,i))
__device__ inline float tf_normal(unsigned k0, unsigned k1, unsigned idx) {
    unsigned x0 = 0u, x1 = idx;
    tf2x32(k0, k1, x0, x1);
    unsigned bits = x0 ^ x1;
    float f = __uint_as_float((bits >> 9) | 0x3f800000u) - 1.0f;
    const float lo = -0.99999994f;
    float u = fmaxf(lo, f * 2.0f + lo);
    return 1.4142135623730951f * erfinv_x(u);
}

// ===========================================================================
// SE(3) helpers — affine 3x4 (12-float); fast MUFU sin/cos (abs err ~1e-7,
// far inside the 1e-3 tolerance; current margin 1.6e-6).
// ===========================================================================
__device__ inline void se3exp12(const float xi[6], float T[12]) {
    float t0 = xi[0], t1 = xi[1], t2 = xi[2];
    float w0 = xi[3], w1 = xi[4], w2 = xi[5];
    float nw = sqrtf(w0 * w0 + w1 * w1 + w2 * w2);
    float theta = fmaxf(nw, 1e-8f);
    float a0 = w0 / theta, a1 = w1 / theta, a2 = w2 / theta;
    float K[9] = { 0.f, -a2,  a1,
                   a2,  0.f, -a0,
                  -a1,  a0,  0.f };
    float KK[9];
#pragma unroll
    for (int i = 0; i < 3; ++i)
#pragma unroll
        for (int j = 0; j < 3; ++j)
            KK[i * 3 + j] = K[i * 3 + 0] * K[0 * 3 + j]
                          + K[i * 3 + 1] * K[1 * 3 + j]
                          + K[i * 3 + 2] * K[2 * 3 + j];
    float st = __sinf(theta);
    float ct = 1.0f - __cosf(theta);
    float cf = ct / theta;
    float sf = 1.0f - st / theta;
    float R[9], V[9];
#pragma unroll
    for (int i = 0; i < 9; ++i) {
        float eye = (i == 0 || i == 4 || i == 8) ? 1.0f : 0.0f;
        R[i] = eye + st * K[i] + ct * KK[i];
        V[i] = eye + cf * K[i] + sf * KK[i];
    }
    T[0] = R[0]; T[1] = R[1]; T[2]  = R[2];
    T[3]  = V[0] * t0 + V[1] * t1 + V[2] * t2;
    T[4] = R[3]; T[5] = R[4]; T[6]  = R[5];
    T[7]  = V[3] * t0 + V[4] * t1 + V[5] * t2;
    T[8] = R[6]; T[9] = R[7]; T[10] = R[8];
    T[11] = V[6] * t0 + V[7] * t1 + V[8] * t2;
}

__device__ inline void compose12(const float A[12], const float B[12], float C[12]) {
#pragma unroll
    for (int i = 0; i < 3; ++i) {
#pragma unroll
        for (int j = 0; j < 4; ++j) {
            float s = A[i * 4 + 0] * B[0 * 4 + j]
                    + A[i * 4 + 1] * B[1 * 4 + j]
                    + A[i * 4 + 2] * B[2 * 4 + j];
            if (j == 3) s += A[i * 4 + 3];
            C[i * 4 + j] = s;
        }
    }
}

__device__ inline void build_hyp12(int m, float n0, float n1, float n2,
                                   const float* Tp, float T[12]) {
    const float DEG = 0.017453292519943295f;
    float xi[6];
    xi[0] = n0; xi[1] = n1; xi[2] = n2;
    xi[3] = 0.0f;
    xi[4] = (float)(-11 + 2 * (m / 12)) * DEG;
    xi[5] = (float)(-11 + 2 * (m % 12)) * DEG;
    float dT[12];
    se3exp12(xi, dT);
    compose12(dT, Tp, T);
}

__device__ inline void mm4(const float A[16], const float B[16], float C[16]) {
#pragma unroll
    for (int i = 0; i < 4; ++i)
#pragma unroll
        for (int j = 0; j < 4; ++j)
            C[i * 4 + j] = A[i * 4 + 0] * B[0 * 4 + j]
                         + A[i * 4 + 1] * B[1 * 4 + j]
                         + A[i * 4 + 2] * B[2 * 4 + j]
                         + A[i * 4 + 3] * B[3 * 4 + j];
}

// ===========================================================================
// Kernel 1: vectorized warp-strip Gram build (PPT=2, float2, unroll 8) — R14.
// ===========================================================================
__device__ __forceinline__ void build_strip2(
        const float* __restrict__ q, const float* __restrict__ r,
        const float* __restrict__ u,
        int C, int H, int W, int offpix, int s, int lane) {
    const unsigned FULL = 0xffffffffu;
    int spr = W >> 6;
    int xt = s & (spr - 1);
    int y  = (s / spr) % H;
    int b  = s / (spr * H);
    int x  = (xt << 6) + (lane << 1);
    int yd = min(y + 1, H - 1);
    int HW = H * W;

    const float* qb = q + (size_t)b * C * HW;
    const float* rb = r + (size_t)b * C * HW;
    int o0 = y * W + x;
    int o1 = yd * W + x;
    bool fix = (lane == 31) && (((xt + 1) << 6) < W);

    float S0 = 0.f, R0 = 0.f, D0 = 0.f, G0 = 0.f, A0 = 0.f;
    float S1 = 0.f, R1 = 0.f, D1 = 0.f, G1 = 0.f, A1 = 0.f;

#pragma unroll 8
    for (int c = 0; c < C; ++c) {
        const float* qc = qb + (size_t)c * HW;
        const float* rc = rb + (size_t)c * HW;
        float2 qa = *reinterpret_cast<const float2*>(qc + o0);
        float2 ra = *reinterpret_cast<const float2*>(rc + o0);
        float2 qd = *reinterpret_cast<const float2*>(qc + o1);
        float2 rd = *reinterpret_cast<const float2*>(rc + o1);
        float da0 = qa.x - ra.x, da1 = qa.y - ra.y;
        float db0 = qd.x - rd.x, db1 = qd.y - rd.y;
        float e0 = __shfl_down_sync(FULL, da0, 1);
        float e1 = __shfl_down_sync(FULL, db0, 1);
        if (lane == 31) {
            if (fix) {
                e0 = qc[o0 + 2] - rc[o0 + 2];
                e1 = qc[o1 + 2] - rc[o1 + 2];
            } else {
                e0 = da1;
                e1 = db1;
            }
        }
        S0 = fmaf(da0, da0, S0);
        R0 = fmaf(da0, da1, R0);
        D0 = fmaf(da0, db0, D0);
        G0 = fmaf(da0, db1, G0);
        A0 = fmaf(da1, db0, A0);
        S1 = fmaf(da1, da1, S1);
        R1 = fmaf(da1, e0,  R1);
        D1 = fmaf(da1, db1, D1);
        G1 = fmaf(da1, e1,  G1);
        A1 = fmaf(e0,  db1, A1);
    }
    float Ua = u[(size_t)b * HW + o0];
    float Ub = u[(size_t)b * HW + o0 + 1];
    int pix = offpix + b * HW + o0;
    g_maps[pix * 2 + 0] = make_float4(S0, R0, D0, G0);
    g_maps[pix * 2 + 1] = make_float4(A0, Ua, 0.f, 0.f);
    g_maps[pix * 2 + 2] = make_float4(S1, R1, D1, G1);
    g_maps[pix * 2 + 3] = make_float4(A1, Ub, 0.f, 0.f);
}

__global__ __launch_bounds__(128, 9)
void build_all_kernel(const float* __restrict__ q0, const float* __restrict__ r0,
                      const float* __restrict__ u0,
                      const float* __restrict__ q1, const float* __restrict__ r1,
                      const float* __restrict__ u1,
                      const float* __restrict__ q2, const float* __restrict__ r2,
                      const float* __restrict__ u2) {
    int wid  = threadIdx.x >> 5;
    int lane = threadIdx.x & 31;
    int gw = blockIdx.x * 4 + wid;
    if (gw < ST0) {
        build_strip2(q0, r0, u0, 128, 48, 64, 0, gw, lane);
    } else if (gw < ST0 + ST1) {
        build_strip2(q1, r1, u1, 64, 96, 128, PX0, gw - ST0, lane);
    } else {
        build_strip2(q2, r2, u2, 32, 192, 256, PX0 + PX1, gw - ST0 - ST1, lane);
    }
}

// ===========================================================================
// Kernel 2: mega kernel — one CTA (512 thr) per (b, m<16); 9 LM iterations.
// CELL CACHE: LM steps are ~1e-6, so the bilinear cell is unchanged between
// consecutive iterations at a level -> cache the 8 float4 records in regs,
// keyed on (level, cell). Reload only on key change (bit-exact).
// ===========================================================================
__global__ __launch_bounds__(512)
void mega_kernel(const float* __restrict__ T_pred,
                 const float* __restrict__ geo,
                 const float* __restrict__ Kin,
                 TFKeys keys) {
    int bm = blockIdx.x;
    int b = bm >> 4;
    int m = bm & 15;
    int tid  = threadIdx.x;
    int wid  = tid >> 5;
    int lane = tid & 31;
    const unsigned FULL = 0xffffffffu;

    __shared__ float wsum[2][16];
    __shared__ float snz[9][6];

    // precompute all 54 iteration-noise values (warp 1, off critical path)
    if (wid == 1) {
        unsigned base = (unsigned)((b * MM + m) * 6);
        if (lane < 54) {
            int it = lane / 6, j = lane % 6;
            snz[it][j] = tf_normal(keys.ik0[it], keys.ik1[it], base + (unsigned)j);
        }
        if (lane + 32 < 54) {
            int l2 = lane + 32;
            int it = l2 / 6, j = l2 % 6;
            snz[it][j] = tf_normal(keys.ik0[it], keys.ik1[it], base + (unsigned)j);
        }
    }

    // initial hypothesis (redundant per warp)
    float nz = 0.f;
    if (lane < 3)
        nz = tf_normal(keys.hk0, keys.hk1, (unsigned)(m * 3 + lane));
    float n0 = __shfl_sync(FULL, nz, 0);
    float n1 = __shfl_sync(FULL, nz, 1);
    float n2 = __shfl_sync(FULL, nz, 2);
    float T[12];
    build_hyp12(m, n0, n1, n2, &T_pred[b * 16], T);

    bool act = tid < NN;
    float X = 0.f, Y = 0.f, Z = 0.f;
    if (act) {
        const float* gp = &geo[(b * NN + tid) * 3];
        X = gp[0]; Y = gp[1]; Z = gp[2];
    }
    float k00 = Kin[b * 9 + 0], k02 = Kin[b * 9 + 2];
    float k11 = Kin[b * 9 + 4], k12 = Kin[b * 9 + 5];

    const int   LH[3]    = {48, 96, 192};
    const int   LW[3]    = {64, 128, 256};
    const int   LOFF[3]  = {0, PX0, PX0 + PX1};
    const float LSC[3]   = {0.25f, 0.5f, 1.0f};
    const float LDAMP[3] = {0.001f, 0.0005f, 0.00025f};

    __syncthreads();   // snz ready

    // cached bilinear cell (8 float4 records) keyed on (level, cell index)
    int pkey = -1;
    float4 a00, b00, a01, b01, a10, b10, a11, b11;
    a00 = b00 = a01 = b01 = a10 = b10 = a11 = b11 = make_float4(0.f, 0.f, 0.f, 0.f);

    float res = 0.f;
    for (int it = 0; it < 9; ++it) {
        int level = (it < 2) ? 0 : ((it < 5) ? 1 : 2);
        int H = LH[level], W = LW[level];
        float sc = LSC[level];
        float fx = k00 * sc, fy = k11 * sc;
        float cx = k02 * sc, cy = k12 * sc;
        const float4* mp = g_maps + (size_t)LOFF[level] * 2;

        float acc = 0.f;
        if (act) {
            float pcx = T[0] * X + T[1] * Y + T[2]  * Z + T[3];
            float pcy = T[4] * X + T[5] * Y + T[6]  * Z + T[7];
            float pcz = T[8] * X + T[9] * Y + T[10] * Z + T[11];
            float z = fmaxf(pcz, 1e-6f);
            float uu = fx * (pcx / z) + cx;
            float vv = fy * (pcy / z) + cy;
            float gx = 2.0f * uu / (float)(W - 1) - 1.0f;
            float gy = 2.0f * vv / (float)(H - 1) - 1.0f;
            float xs = ((gx + 1.0f) * (float)W - 1.0f) * 0.5f;
            float ys = ((gy + 1.0f) * (float)H - 1.0f) * 0.5f;
            xs = fminf(fmaxf(xs, 0.0f), (float)(W - 1));
            ys = fminf(fmaxf(ys, 0.0f), (float)(H - 1));
            float fx0 = floorf(xs), fy0 = floorf(ys);
            float wx = xs - fx0, wy = ys - fy0;
            int x0 = (int)fx0, y0 = (int)fy0;
            int lin = (b * H + y0) * W + x0;
            int key = (level << 20) | lin;
            if (key != pkey) {
                pkey = key;
                int x1 = min(x0 + 1, W - 1);
                int y1 = min(y0 + 1, H - 1);
                int rowb = (b * H + y0) * W;
                int rowd = (b * H + y1) * W;
                int i00 = (rowb + x0) * 2, i01 = (rowb + x1) * 2;
                int i10 = (rowd + x0) * 2, i11 = (rowd + x1) * 2;
                a00 = mp[i00]; b00 = mp[i00 + 1];
                a01 = mp[i01]; b01 = mp[i01 + 1];
                a10 = mp[i10]; b10 = mp[i10 + 1];
                a11 = mp[i11]; b11 = mp[i11 + 1];
            }
            float w00 = (1.f - wx) * (1.f - wy);
            float w01 = wx * (1.f - wy);
            float w10 = (1.f - wx) * wy;
            float w11 = wx * wy;
            float qrs = w00 * w00 * a00.x + w01 * w01 * a01.x
                      + w10 * w10 * a10.x + w11 * w11 * a11.x
                      + 2.f * (w00 * w01 * a00.y + w10 * w11 * a10.y
                             + w00 * w10 * a00.z + w01 * w11 * a01.z
                             + w00 * w11 * a00.w + w01 * w10 * b00.x);
            float un = w00 * b00.y + w01 * b01.y + w10 * b10.y + w11 * b11.y;
            acc = qrs * un;
        }
        acc += __shfl_xor_sync(FULL, acc, 16);
        acc += __shfl_xor_sync(FULL, acc, 8);
        acc += __shfl_xor_sync(FULL, acc, 4);
        acc += __shfl_xor_sync(FULL, acc, 2);
        acc += __shfl_xor_sync(FULL, acc, 1);
        if (lane == 0) wsum[it & 1][wid] = acc;
        __syncthreads();

        // redundant update in ALL threads (identical result, no 2nd barrier)
        float rsum = 0.f;
#pragma unroll
        for (int w = 0; w < 16; ++w) rsum += wsum[it & 1][w];
        res = rsum / 500.0f;

        float nd = -LDAMP[level] * res * 0.01f;
        float stp[6];
#pragma unroll
        for (int j = 0; j < 6; ++j) stp[j] = nd * snz[it][j];
        float dT[12], Tn[12];
        se3exp12(stp, dT);
        compose12(dT, T, Tn);
#pragma unroll
        for (int k = 0; k < 12; ++k) T[k] = Tn[k];
    }

    if (tid == 0) {
        g_costs[b * M16 + m] = res;
#pragma unroll
        for (int k = 0; k < 12; ++k)
            g_Tcur[(b * M16 + m) * 12 + k] = T[k];
    }
}

// ===========================================================================
// Kernel 3: finalize — geodesic + argmin + outputs
// ===========================================================================
__global__ __launch_bounds__(256)
void finalize_kernel(const float* __restrict__ T_pred,
                     float* __restrict__ out, TFKeys keys) {
    int b = blockIdx.x;
    int tid = threadIdx.x;
    int m = tid;
    __shared__ float sv[256];
    __shared__ int si[256];

    const float* Tp = &T_pred[b * 16];
    float T[16];
#pragma unroll
    for (int k = 0; k < 16; ++k) T[k] = 0.f;
    T[15] = 1.f;
    float cost = 0.f;
    float total = 3.0e38f;

    if (m < MM) {
        if (m < M16) {
#pragma unroll
            for (int k = 0; k < 12; ++k) T[k] = g_Tcur[(b * M16 + m) * 12 + k];
            cost = g_costs[b * M16 + m];
        } else {
            float n0 = tf_normal(keys.hk0, keys.hk1, (unsigned)(m * 3 + 0));
            float n1 = tf_normal(keys.hk0, keys.hk1, (unsigned)(m * 3 + 1));
            float n2 = tf_normal(keys.hk0, keys.hk1, (unsigned)(m * 3 + 2));
            float T12[12];
            build_hyp12(m, n0, n1, n2, Tp, T12);
#pragma unroll
            for (int k = 0; k < 12; ++k) T[k] = T12[k];
        }
        float Ti[16];
        Ti[0] = Tp[0]; Ti[1] = Tp[4]; Ti[2]  = Tp[8];
        Ti[4] = Tp[1]; Ti[5] = Tp[5]; Ti[6]  = Tp[9];
        Ti[8] = Tp[2]; Ti[9] = Tp[6]; Ti[10] = Tp[10];
        Ti[3]  = -(Ti[0] * Tp[3] + Ti[1] * Tp[7] + Ti[2]  * Tp[11]);
        Ti[7]  = -(Ti[4] * Tp[3] + Ti[5] * Tp[7] + Ti[6]  * Tp[11]);
        Ti[11] = -(Ti[8] * Tp[3] + Ti[9] * Tp[7] + Ti[10] * Tp[11]);
        Ti[12] = 0.f; Ti[13] = 0.f; Ti[14] = 0.f; Ti[15] = 1.f;

        float Tr[16];
        mm4(T, Ti, Tr);

        float tr = Tr[0] + Tr[5] + Tr[10];
        float ca = (tr - 1.0f) * 0.5f;
        ca = fminf(fmaxf(ca, -1.0f + 1e-7f), 1.0f - 1e-7f);
        float theta = acosf(ca);
        float th = fmaxf(theta, 1e-8f);
        float sn = fmaxf(sinf(th), 1e-8f);
        float fac = th / (2.0f * sn);
        float w0 = (Tr[9] - Tr[6]) * fac;
        float w1 = (Tr[2] - Tr[8]) * fac;
        float w2 = (Tr[4] - Tr[1]) * fac;
        if (fabsf(theta) < 1e-6f) { w0 = 0.f; w1 = 0.f; w2 = 0.f; }
        float t0 = Tr[3], t1 = Tr[7], t2 = Tr[11];
        float geod = sqrtf(t0 * t0 + t1 * t1 + t2 * t2
                         + w0 * w0 + w1 * w1 + w2 * w2);
        total = cost + geod;
    }

    sv[tid] = total;
    si[tid] = tid;
    __syncthreads();
    for (int s = 128; s > 0; s >>= 1) {
        if (tid < s) {
            if (sv[tid + s] < sv[tid]) {
                sv[tid] = sv[tid + s];
                si[tid] = si[tid + s];
            }
        }
        __syncthreads();
    }
    int best = si[0];

    if (m == best) {
#pragma unroll
        for (int k = 0; k < 16; ++k) out[b * 16 + k] = T[k];
    }
    if (m < MM) out[BB * 16 + b * MM + m] = cost;
}

// ===========================================================================
// Launch (single stream, sequential — proven path)
// ===========================================================================
extern "C" void kernel_launch(void* const* d_in, const int* in_sizes, int n_in,
                              void* d_out, int out_size) {
    (void)in_sizes; (void)n_in; (void)out_size;
    const float* T_pred = (const float*)d_in[0];
    const float* geo    = (const float*)d_in[1];
    const float* K      = (const float*)d_in[2];
    const float* q0 = (const float*)d_in[3];
    const float* q1 = (const float*)d_in[4];
    const float* q2 = (const float*)d_in[5];
    const float* r0 = (const float*)d_in[6];
    const float* r1 = (const float*)d_in[7];
    const float* r2 = (const float*)d_in[8];
    const float* u0 = (const float*)d_in[9];
    const float* u1 = (const float*)d_in[10];
    const float* u2 = (const float*)d_in[11];
    float* out = (float*)d_out;

    TFKeys keys;
    {
        unsigned x0 = 0, x1 = 0;
        tf2x32(0u, 42u, x0, x1);
        keys.hk0 = x0; keys.hk1 = x1;
        const unsigned ds[9] = {100u, 101u, 110u, 111u, 112u,
                                120u, 121u, 122u, 123u};
        for (int i = 0; i < 9; ++i) {
            unsigned a = 0, bb2 = ds[i];
            tf2x32(0u, 42u, a, bb2);
            keys.ik0[i] = a; keys.ik1[i] = bb2;
        }
    }

    build_all_kernel<<<NCTAS, 128>>>(q0, r0, u0, q1, r1, u1, q2, r2, u2);
    mega_kernel<<<BB * M16, 512>>>(T_pred, geo, K, keys);
    finalize_kernel<<<BB, 256>>>(T_pred, out, keys);
}

// round 16
// speedup vs baseline: 1.4757x; 1.0459x over previous
#include <cuda_runtime.h>
#include <math.h>

// ===========================================================================
// Problem constants
// ===========================================================================
#define BB 8
#define MM 144
#define M16 16
#define NN 500

// L0: C=128 H=48 W=64 | L1: C=64 H=96 W=128 | L2: C=32 H=192 W=256
#define PX0 (8*48*64)     /* 24576  */
#define PX1 (8*96*128)    /* 98304  */
#define PX2 (8*192*256)   /* 393216 */

// strips: PPT=2 everywhere -> warp covers 64 consecutive x; 4 warps per CTA
#define ST0 (8*48)        /* 384  */
#define ST1 (8*96*2)      /* 1536 */
#define ST2 (8*192*4)     /* 6144 */
#define NSTRIPS (ST0+ST1+ST2)   /* 8064 */
#define NCTAS (NSTRIPS/4)       /* 2016 */

// Gram/unc maps: per pixel a 32B record {S,R,D,G | A,U,0,0} as two float4
__device__ float4 g_maps[(PX0 + PX1 + PX2) * 2];
__device__ float  g_Tcur[BB * M16 * 12];
__device__ float  g_costs[BB * M16];

// ===========================================================================
// Threefry2x32 (JAX-compatible, 20 rounds)
// ===========================================================================
__host__ __device__ inline void tf2x32(unsigned k0, unsigned k1,
                                       unsigned& x0, unsigned& x1) {
    unsigned ks2 = k0 ^ k1 ^ 0x1BD11BDAu;
    x0 += k0; x1 += k1;
#define TF_RND(r) { x0 += x1; x1 = (x1 << (r)) | (x1 >> (32 - (r))); x1 ^= x0; }
    TF_RND(13) TF_RND(15) TF_RND(26) TF_RND(6)
    x0 += k1; x1 += ks2 + 1u;
    TF_RND(17) TF_RND(29) TF_RND(16) TF_RND(24)
    x0 += ks2; x1 += k0 + 2u;
    TF_RND(13) TF_RND(15) TF_RND(26) TF_RND(6)
    x0 += k0; x1 += k1 + 3u;
    TF_RND(17) TF_RND(29) TF_RND(16) TF_RND(24)
    x0 += k1; x1 += ks2 + 4u;
    TF_RND(13) TF_RND(15) TF_RND(26) TF_RND(6)
    x0 += ks2; x1 += k0 + 5u;
#undef TF_RND
}

struct TFKeys {
    unsigned hk0, hk1;
    unsigned ik0[9], ik1[9];
};

// XLA ErfInv (float32, Giles polynomial)
__device__ inline float erfinv_x(float x) {
    float w = -log1pf(-x * x);
    float p;
    if (w < 5.0f) {
        w = w - 2.5f;
        p = 2.81022636e-08f;
        p = fmaf(p, w, 3.43273939e-07f);
        p = fmaf(p, w, -3.5233877e-06f);
        p = fmaf(p, w, -4.39150654e-06f);
        p = fmaf(p, w, 0.00021858087f);
        p = fmaf(p, w, -0.00125372503f);
        p = fmaf(p, w, -0.00417768164f);
        p = fmaf(p, w, 0.246640727f);
        p = fmaf(p, w, 1.50140941f);
    } else {
        w = sqrtf(w) - 3.0f;
        p = -0.000200214257f;
        p = fmaf(p, w, 0.000100950558f);
        p = fmaf(p, w, 0.00134934322f);
        p = fmaf(p, w, -0.00367342844f);
        p = fmaf(p, w, 0.00573950773f);
        p = fmaf(p, w, -0.0076224613f);
        p = fmaf(p, w, 0.00943887047f);
        p = fmaf(p, w, 1.00167406f);
        p = fmaf(p, w, 2.83297682f);
    }
    return p * x;
}

// jax.random.normal, partitionable threefry: bits[i] = x0 ^ x1 of enc(key,(0,i))
__device__ inline float tf_normal(unsigned k0, unsigned k1, unsigned idx) {
    unsigned x0 = 0u, x1 = idx;
    tf2x32(k0, k1, x0, x1);
    unsigned bits = x0 ^ x1;
    float f = __uint_as_float((bits >> 9) | 0x3f800000u) - 1.0f;
    const float lo = -0.99999994f;
    float u = fmaxf(lo, f * 2.0f + lo);
    return 1.4142135623730951f * erfinv_x(u);
}

// ===========================================================================
// SE(3) helpers — affine 3x4 (12-float); MUFU sin/cos (err ~1e-7 << 1e-3 tol)
// ===========================================================================
__device__ inline void se3exp12(const float xi[6], float T[12]) {
    float t0 = xi[0], t1 = xi[1], t2 = xi[2];
    float w0 = xi[3], w1 = xi[4], w2 = xi[5];
    float nw = sqrtf(w0 * w0 + w1 * w1 + w2 * w2);
    float theta = fmaxf(nw, 1e-8f);
    float a0 = w0 / theta, a1 = w1 / theta, a2 = w2 / theta;
    float K[9] = { 0.f, -a2,  a1,
                   a2,  0.f, -a0,
                  -a1,  a0,  0.f };
    float KK[9];
#pragma unroll
    for (int i = 0; i < 3; ++i)
#pragma unroll
        for (int j = 0; j < 3; ++j)
            KK[i * 3 + j] = K[i * 3 + 0] * K[0 * 3 + j]
                          + K[i * 3 + 1] * K[1 * 3 + j]
                          + K[i * 3 + 2] * K[2 * 3 + j];
    float st = __sinf(theta);
    float ct = 1.0f - __cosf(theta);
    float cf = ct / theta;
    float sf = 1.0f - st / theta;
    float R[9], V[9];
#pragma unroll
    for (int i = 0; i < 9; ++i) {
        float eye = (i == 0 || i == 4 || i == 8) ? 1.0f : 0.0f;
        R[i] = eye + st * K[i] + ct * KK[i];
        V[i] = eye + cf * K[i] + sf * KK[i];
    }
    T[0] = R[0]; T[1] = R[1]; T[2]  = R[2];
    T[3]  = V[0] * t0 + V[1] * t1 + V[2] * t2;
    T[4] = R[3]; T[5] = R[4]; T[6]  = R[5];
    T[7]  = V[3] * t0 + V[4] * t1 + V[5] * t2;
    T[8] = R[6]; T[9] = R[7]; T[10] = R[8];
    T[11] = V[6] * t0 + V[7] * t1 + V[8] * t2;
}

__device__ inline void compose12(const float A[12], const float B[12], float C[12]) {
#pragma unroll
    for (int i = 0; i < 3; ++i) {
#pragma unroll
        for (int j = 0; j < 4; ++j) {
            float s = A[i * 4 + 0] * B[0 * 4 + j]
                    + A[i * 4 + 1] * B[1 * 4 + j]
                    + A[i * 4 + 2] * B[2 * 4 + j];
            if (j == 3) s += A[i * 4 + 3];
            C[i * 4 + j] = s;
        }
    }
}

__device__ inline void build_hyp12(int m, float n0, float n1, float n2,
                                   const float* Tp, float T[12]) {
    const float DEG = 0.017453292519943295f;
    float xi[6];
    xi[0] = n0; xi[1] = n1; xi[2] = n2;
    xi[3] = 0.0f;
    xi[4] = (float)(-11 + 2 * (m / 12)) * DEG;
    xi[5] = (float)(-11 + 2 * (m % 12)) * DEG;
    float dT[12];
    se3exp12(xi, dT);
    compose12(dT, Tp, T);
}

__device__ inline void mm4(const float A[16], const float B[16], float C[16]) {
#pragma unroll
    for (int i = 0; i < 4; ++i)
#pragma unroll
        for (int j = 0; j < 4; ++j)
            C[i * 4 + j] = A[i * 4 + 0] * B[0 * 4 + j]
                         + A[i * 4 + 1] * B[1 * 4 + j]
                         + A[i * 4 + 2] * B[2 * 4 + j]
                         + A[i * 4 + 3] * B[3 * 4 + j];
}

// ===========================================================================
// Kernel 1: vectorized warp-strip Gram build (PPT=2, float2, unroll 16).
// launch_bounds(128,8): reg budget 64 for the wider load batch.
// ===========================================================================
__device__ __forceinline__ void build_strip2(
        const float* __restrict__ q, const float* __restrict__ r,
        const float* __restrict__ u,
        int C, int H, int W, int offpix, int s, int lane) {
    const unsigned FULL = 0xffffffffu;
    int spr = W >> 6;
    int xt = s & (spr - 1);
    int y  = (s / spr) % H;
    int b  = s / (spr * H);
    int x  = (xt << 6) + (lane << 1);
    int yd = min(y + 1, H - 1);
    int HW = H * W;

    const float* qb = q + (size_t)b * C * HW;
    const float* rb = r + (size_t)b * C * HW;
    int o0 = y * W + x;
    int o1 = yd * W + x;
    bool fix = (lane == 31) && (((xt + 1) << 6) < W);

    float S0 = 0.f, R0 = 0.f, D0 = 0.f, G0 = 0.f, A0 = 0.f;
    float S1 = 0.f, R1 = 0.f, D1 = 0.f, G1 = 0.f, A1 = 0.f;

#pragma unroll 16
    for (int c = 0; c < C; ++c) {
        const float* qc = qb + (size_t)c * HW;
        const float* rc = rb + (size_t)c * HW;
        float2 qa = *reinterpret_cast<const float2*>(qc + o0);
        float2 ra = *reinterpret_cast<const float2*>(rc + o0);
        float2 qd = *reinterpret_cast<const float2*>(qc + o1);
        float2 rd = *reinterpret_cast<const float2*>(rc + o1);
        float da0 = qa.x - ra.x, da1 = qa.y - ra.y;
        float db0 = qd.x - rd.x, db1 = qd.y - rd.y;
        float e0 = __shfl_down_sync(FULL, da0, 1);
        float e1 = __shfl_down_sync(FULL, db0, 1);
        if (lane == 31) {
            if (fix) {
                e0 = qc[o0 + 2] - rc[o0 + 2];
                e1 = qc[o1 + 2] - rc[o1 + 2];
            } else {
                e0 = da1;
                e1 = db1;
            }
        }
        S0 = fmaf(da0, da0, S0);
        R0 = fmaf(da0, da1, R0);
        D0 = fmaf(da0, db0, D0);
        G0 = fmaf(da0, db1, G0);
        A0 = fmaf(da1, db0, A0);
        S1 = fmaf(da1, da1, S1);
        R1 = fmaf(da1, e0,  R1);
        D1 = fmaf(da1, db1, D1);
        G1 = fmaf(da1, e1,  G1);
        A1 = fmaf(e0,  db1, A1);
    }
    float Ua = u[(size_t)b * HW + o0];
    float Ub = u[(size_t)b * HW + o0 + 1];
    int pix = offpix + b * HW + o0;
    g_maps[pix * 2 + 0] = make_float4(S0, R0, D0, G0);
    g_maps[pix * 2 + 1] = make_float4(A0, Ua, 0.f, 0.f);
    g_maps[pix * 2 + 2] = make_float4(S1, R1, D1, G1);
    g_maps[pix * 2 + 3] = make_float4(A1, Ub, 0.f, 0.f);
}

__global__ __launch_bounds__(128, 8)
void build_all_kernel(const float* __restrict__ q0, const float* __restrict__ r0,
                      const float* __restrict__ u0,
                      const float* __restrict__ q1, const float* __restrict__ r1,
                      const float* __restrict__ u1,
                      const float* __restrict__ q2, const float* __restrict__ r2,
                      const float* __restrict__ u2) {
    int wid  = threadIdx.x >> 5;
    int lane = threadIdx.x & 31;
    int gw = blockIdx.x * 4 + wid;
    if (gw < ST0) {
        build_strip2(q0, r0, u0, 128, 48, 64, 0, gw, lane);
    } else if (gw < ST0 + ST1) {
        build_strip2(q1, r1, u1, 64, 96, 128, PX0, gw - ST0, lane);
    } else {
        build_strip2(q2, r2, u2, 32, 192, 256, PX0 + PX1, gw - ST0 - ST1, lane);
    }
}

// ===========================================================================
// Kernel 2: mega kernel — one CTA (512 thr) per (b, m<16); 9 LM iterations.
// Register-resident pose, cell cache, 1 barrier/iter, precomputed noise.
// ===========================================================================
__global__ __launch_bounds__(512)
void mega_kernel(const float* __restrict__ T_pred,
                 const float* __restrict__ geo,
                 const float* __restrict__ Kin,
                 TFKeys keys) {
    int bm = blockIdx.x;
    int b = bm >> 4;
    int m = bm & 15;
    int tid  = threadIdx.x;
    int wid  = tid >> 5;
    int lane = tid & 31;
    const unsigned FULL = 0xffffffffu;

    __shared__ float wsum[2][16];
    __shared__ float snz[9][6];

    if (wid == 1) {
        unsigned base = (unsigned)((b * MM + m) * 6);
        if (lane < 54) {
            int it = lane / 6, j = lane % 6;
            snz[it][j] = tf_normal(keys.ik0[it], keys.ik1[it], base + (unsigned)j);
        }
        if (lane + 32 < 54) {
            int l2 = lane + 32;
            int it = l2 / 6, j = l2 % 6;
            snz[it][j] = tf_normal(keys.ik0[it], keys.ik1[it], base + (unsigned)j);
        }
    }

    float nz = 0.f;
    if (lane < 3)
        nz = tf_normal(keys.hk0, keys.hk1, (unsigned)(m * 3 + lane));
    float n0 = __shfl_sync(FULL, nz, 0);
    float n1 = __shfl_sync(FULL, nz, 1);
    float n2 = __shfl_sync(FULL, nz, 2);
    float T[12];
    build_hyp12(m, n0, n1, n2, &T_pred[b * 16], T);

    bool act = tid < NN;
    float X = 0.f, Y = 0.f, Z = 0.f;
    if (act) {
        const float* gp = &geo[(b * NN + tid) * 3];
        X = gp[0]; Y = gp[1]; Z = gp[2];
    }
    float k00 = Kin[b * 9 + 0], k02 = Kin[b * 9 + 2];
    float k11 = Kin[b * 9 + 4], k12 = Kin[b * 9 + 5];

    const int   LH[3]    = {48, 96, 192};
    const int   LW[3]    = {64, 128, 256};
    const int   LOFF[3]  = {0, PX0, PX0 + PX1};
    const float LSC[3]   = {0.25f, 0.5f, 1.0f};
    const float LDAMP[3] = {0.001f, 0.0005f, 0.00025f};

    __syncthreads();   // snz ready

    int pkey = -1;
    float4 a00, b00, a01, b01, a10, b10, a11, b11;
    a00 = b00 = a01 = b01 = a10 = b10 = a11 = b11 = make_float4(0.f, 0.f, 0.f, 0.f);

    float res = 0.f;
    for (int it = 0; it < 9; ++it) {
        int level = (it < 2) ? 0 : ((it < 5) ? 1 : 2);
        int H = LH[level], W = LW[level];
        float sc = LSC[level];
        float fx = k00 * sc, fy = k11 * sc;
        float cx = k02 * sc, cy = k12 * sc;
        const float4* mp = g_maps + (size_t)LOFF[level] * 2;

        float acc = 0.f;
        if (act) {
            float pcx = T[0] * X + T[1] * Y + T[2]  * Z + T[3];
            float pcy = T[4] * X + T[5] * Y + T[6]  * Z + T[7];
            float pcz = T[8] * X + T[9] * Y + T[10] * Z + T[11];
            float z = fmaxf(pcz, 1e-6f);
            float uu = fx * (pcx / z) + cx;
            float vv = fy * (pcy / z) + cy;
            float gx = 2.0f * uu / (float)(W - 1) - 1.0f;
            float gy = 2.0f * vv / (float)(H - 1) - 1.0f;
            float xs = ((gx + 1.0f) * (float)W - 1.0f) * 0.5f;
            float ys = ((gy + 1.0f) * (float)H - 1.0f) * 0.5f;
            xs = fminf(fmaxf(xs, 0.0f), (float)(W - 1));
            ys = fminf(fmaxf(ys, 0.0f), (float)(H - 1));
            float fx0 = floorf(xs), fy0 = floorf(ys);
            float wx = xs - fx0, wy = ys - fy0;
            int x0 = (int)fx0, y0 = (int)fy0;
            int lin = (b * H + y0) * W + x0;
            int key = (level << 20) | lin;
            if (key != pkey) {
                pkey = key;
                int x1 = min(x0 + 1, W - 1);
                int y1 = min(y0 + 1, H - 1);
                int rowb = (b * H + y0) * W;
                int rowd = (b * H + y1) * W;
                int i00 = (rowb + x0) * 2, i01 = (rowb + x1) * 2;
                int i10 = (rowd + x0) * 2, i11 = (rowd + x1) * 2;
                a00 = mp[i00]; b00 = mp[i00 + 1];
                a01 = mp[i01]; b01 = mp[i01 + 1];
                a10 = mp[i10]; b10 = mp[i10 + 1];
                a11 = mp[i11]; b11 = mp[i11 + 1];
            }
            float w00 = (1.f - wx) * (1.f - wy);
            float w01 = wx * (1.f - wy);
            float w10 = (1.f - wx) * wy;
            float w11 = wx * wy;
            float qrs = w00 * w00 * a00.x + w01 * w01 * a01.x
                      + w10 * w10 * a10.x + w11 * w11 * a11.x
                      + 2.f * (w00 * w01 * a00.y + w10 * w11 * a10.y
                             + w00 * w10 * a00.z + w01 * w11 * a01.z
                             + w00 * w11 * a00.w + w01 * w10 * b00.x);
            float un = w00 * b00.y + w01 * b01.y + w10 * b10.y + w11 * b11.y;
            acc = qrs * un;
        }
        acc += __shfl_xor_sync(FULL, acc, 16);
        acc += __shfl_xor_sync(FULL, acc, 8);
        acc += __shfl_xor_sync(FULL, acc, 4);
        acc += __shfl_xor_sync(FULL, acc, 2);
        acc += __shfl_xor_sync(FULL, acc, 1);
        if (lane == 0) wsum[it & 1][wid] = acc;
        __syncthreads();

        float rsum = 0.f;
#pragma unroll
        for (int w = 0; w < 16; ++w) rsum += wsum[it & 1][w];
        res = rsum / 500.0f;

        float nd = -LDAMP[level] * res * 0.01f;
        float stp[6];
#pragma unroll
        for (int j = 0; j < 6; ++j) stp[j] = nd * snz[it][j];
        float dT[12], Tn[12];
        se3exp12(stp, dT);
        compose12(dT, T, Tn);
#pragma unroll
        for (int k = 0; k < 12; ++k) T[k] = Tn[k];
    }

    if (tid == 0) {
        g_costs[b * M16 + m] = res;
#pragma unroll
        for (int k = 0; k < 12; ++k)
            g_Tcur[(b * M16 + m) * 12 + k] = T[k];
    }
}

// ===========================================================================
// Kernel 3: finalize — geodesic + argmin + outputs
// ===========================================================================
__global__ __launch_bounds__(256)
void finalize_kernel(const float* __restrict__ T_pred,
                     float* __restrict__ out, TFKeys keys) {
    int b = blockIdx.x;
    int tid = threadIdx.x;
    int m = tid;
    __shared__ float sv[256];
    __shared__ int si[256];

    const float* Tp = &T_pred[b * 16];
    float T[16];
#pragma unroll
    for (int k = 0; k < 16; ++k) T[k] = 0.f;
    T[15] = 1.f;
    float cost = 0.f;
    float total = 3.0e38f;

    if (m < MM) {
        if (m < M16) {
#pragma unroll
            for (int k = 0; k < 12; ++k) T[k] = g_Tcur[(b * M16 + m) * 12 + k];
            cost = g_costs[b * M16 + m];
        } else {
            float n0 = tf_normal(keys.hk0, keys.hk1, (unsigned)(m * 3 + 0));
            float n1 = tf_normal(keys.hk0, keys.hk1, (unsigned)(m * 3 + 1));
            float n2 = tf_normal(keys.hk0, keys.hk1, (unsigned)(m * 3 + 2));
            float T12[12];
            build_hyp12(m, n0, n1, n2, Tp, T12);
#pragma unroll
            for (int k = 0; k < 12; ++k) T[k] = T12[k];
        }
        float Ti[16];
        Ti[0] = Tp[0]; Ti[1] = Tp[4]; Ti[2]  = Tp[8];
        Ti[4] = Tp[1]; Ti[5] = Tp[5]; Ti[6]  = Tp[9];
        Ti[8] = Tp[2]; Ti[9] = Tp[6]; Ti[10] = Tp[10];
        Ti[3]  = -(Ti[0] * Tp[3] + Ti[1] * Tp[7] + Ti[2]  * Tp[11]);
        Ti[7]  = -(Ti[4] * Tp[3] + Ti[5] * Tp[7] + Ti[6]  * Tp[11]);
        Ti[11] = -(Ti[8] * Tp[3] + Ti[9] * Tp[7] + Ti[10] * Tp[11]);
        Ti[12] = 0.f; Ti[13] = 0.f; Ti[14] = 0.f; Ti[15] = 1.f;

        float Tr[16];
        mm4(T, Ti, Tr);

        float tr = Tr[0] + Tr[5] + Tr[10];
        float ca = (tr - 1.0f) * 0.5f;
        ca = fminf(fmaxf(ca, -1.0f + 1e-7f), 1.0f - 1e-7f);
        float theta = acosf(ca);
        float th = fmaxf(theta, 1e-8f);
        float sn = fmaxf(sinf(th), 1e-8f);
        float fac = th / (2.0f * sn);
        float w0 = (Tr[9] - Tr[6]) * fac;
        float w1 = (Tr[2] - Tr[8]) * fac;
        float w2 = (Tr[4] - Tr[1]) * fac;
        if (fabsf(theta) < 1e-6f) { w0 = 0.f; w1 = 0.f; w2 = 0.f; }
        float t0 = Tr[3], t1 = Tr[7], t2 = Tr[11];
        float geod = sqrtf(t0 * t0 + t1 * t1 + t2 * t2
                         + w0 * w0 + w1 * w1 + w2 * w2);
        total = cost + geod;
    }

    sv[tid] = total;
    si[tid] = tid;
    __syncthreads();
    for (int s = 128; s > 0; s >>= 1) {
        if (tid < s) {
            if (sv[tid + s] < sv[tid]) {
                sv[tid] = sv[tid + s];
                si[tid] = si[tid + s];
            }
        }
        __syncthreads();
    }
    int best = si[0];

    if (m == best) {
#pragma unroll
        for (int k = 0; k < 16; ++k) out[b * 16 + k] = T[k];
    }
    if (m < MM) out[BB * 16 + b * MM + m] = cost;
}

// ===========================================================================
// Launch (single stream, sequential — proven path)
// ===========================================================================
extern "C" void kernel_launch(void* const* d_in, const int* in_sizes, int n_in,
                              void* d_out, int out_size) {
    (void)in_sizes; (void)n_in; (void)out_size;
    const float* T_pred = (const float*)d_in[0];
    const float* geo    = (const float*)d_in[1];
    const float* K      = (const float*)d_in[2];
    const float* q0 = (const float*)d_in[3];
    const float* q1 = (const float*)d_in[4];
    const float* q2 = (const float*)d_in[5];
    const float* r0 = (const float*)d_in[6];
    const float* r1 = (const float*)d_in[7];
    const float* r2 = (const float*)d_in[8];
    const float* u0 = (const float*)d_in[9];
    const float* u1 = (const float*)d_in[10];
    const float* u2 = (const float*)d_in[11];
    float* out = (float*)d_out;

    TFKeys keys;
    {
        unsigned x0 = 0, x1 = 0;
        tf2x32(0u, 42u, x0, x1);
        keys.hk0 = x0; keys.hk1 = x1;
        const unsigned ds[9] = {100u, 101u, 110u, 111u, 112u,
                                120u, 121u, 122u, 123u};
        for (int i = 0; i < 9; ++i) {
            unsigned a = 0, bb2 = ds[i];
            tf2x32(0u, 42u, a, bb2);
            keys.ik0[i] = a; keys.ik1[i] = bb2;
        }
    }

    build_all_kernel<<<NCTAS, 128>>>(q0, r0, u0, q1, r1, u1, q2, r2, u2);
    mega_kernel<<<BB * M16, 512>>>(T_pred, geo, K, keys);
    finalize_kernel<<<BB, 256>>>(T_pred, out, keys);
}